// round 13
// baseline (speedup 1.0000x reference)
#include <cuda_runtime.h>
#include <cuda_bf16.h>
#include <math.h>
#include <stdint.h>

#define EMBED 1024
#define NTOK  8192
#define CAP   128
#define WINDOW 700.0f
#define FP8_SCALE   0.015625f   // 1/64 applied to Q,K before e4m3
#define LOGIT_SCALE 128.0f      // (64*64)/32 to undo fp8 scaling and apply 1/sqrt(d)

// ---------------- scratch (device globals) ----------------
__device__ float          g_Q[(size_t)NTOK * EMBED];
__device__ float          g_K[(size_t)NTOK * EMBED];
__device__ __nv_bfloat16  g_Xhi[(size_t)NTOK * EMBED];
__device__ __nv_bfloat16  g_Xlo[(size_t)NTOK * EMBED];
__device__ __nv_bfloat16  g_Wrhi[(size_t)EMBED * EMBED];
__device__ __nv_bfloat16  g_Wrlo[(size_t)EMBED * EMBED];
__device__ __nv_bfloat16  g_Wehi[(size_t)EMBED * EMBED];
__device__ __nv_bfloat16  g_Welo[(size_t)EMBED * EMBED];
__device__ uint8_t        g_Q8[(size_t)NTOK * EMBED];
__device__ uint8_t        g_K8[(size_t)NTOK * EMBED];
__device__ __nv_bfloat16  g_S[(size_t)NTOK * NTOK];
__device__ unsigned       g_rowmax[NTOK];

// ---------------- helpers ----------------
__device__ __forceinline__ uint32_t smem_u32(const void* p) {
    uint32_t a;
    asm("{ .reg .u64 t; cvta.to.shared.u64 t, %1; cvt.u32.u64 %0, t; }" : "=r"(a) : "l"(p));
    return a;
}
__device__ __forceinline__ void cp_async16(uint32_t s, const void* g) {
    asm volatile("cp.async.cg.shared.global [%0], [%1], 16;" :: "r"(s), "l"(g));
}
__device__ __forceinline__ void cp_commit() { asm volatile("cp.async.commit_group;" ::: "memory"); }
template<int N>
__device__ __forceinline__ void cp_wait() { asm volatile("cp.async.wait_group %0;" :: "n"(N) : "memory"); }

__device__ __forceinline__ void ldsm_x4(uint32_t& r0, uint32_t& r1, uint32_t& r2, uint32_t& r3, uint32_t a) {
    asm volatile("ldmatrix.sync.aligned.m8n8.x4.shared.b16 {%0,%1,%2,%3}, [%4];"
                 : "=r"(r0), "=r"(r1), "=r"(r2), "=r"(r3) : "r"(a));
}
__device__ __forceinline__ void mma_bf16(float* d, const uint32_t* a, uint32_t b0, uint32_t b1) {
    asm volatile(
        "mma.sync.aligned.m16n8k16.row.col.f32.bf16.bf16.f32 "
        "{%0,%1,%2,%3}, {%4,%5,%6,%7}, {%8,%9}, {%0,%1,%2,%3};"
        : "+f"(d[0]), "+f"(d[1]), "+f"(d[2]), "+f"(d[3])
        : "r"(a[0]), "r"(a[1]), "r"(a[2]), "r"(a[3]), "r"(b0), "r"(b1));
}
__device__ __forceinline__ void mma_e4m3(float* d, const uint32_t* a, uint32_t b0, uint32_t b1) {
    asm volatile(
        "mma.sync.aligned.m16n8k32.row.col.f32.e4m3.e4m3.f32 "
        "{%0,%1,%2,%3}, {%4,%5,%6,%7}, {%8,%9}, {%0,%1,%2,%3};"
        : "+f"(d[0]), "+f"(d[1]), "+f"(d[2]), "+f"(d[3])
        : "r"(a[0]), "r"(a[1]), "r"(a[2]), "r"(a[3]), "r"(b0), "r"(b1));
}
__device__ __forceinline__ uint16_t pack_e4m3x2(float v0, float v1) {
    uint16_t r;
    asm("cvt.rn.satfinite.e4m3x2.f32 %0, %1, %2;" : "=h"(r) : "f"(v1), "f"(v0));
    return r;   // byte0 = v0, byte1 = v1
}

__device__ __forceinline__ unsigned enc_ord(float f) {
    unsigned u = __float_as_uint(f);
    return (u & 0x80000000u) ? ~u : (u | 0x80000000u);
}
__device__ __forceinline__ float dec_ord(unsigned k) {
    unsigned u = (k & 0x80000000u) ? (k ^ 0x80000000u) : ~k;
    return __uint_as_float(u);
}

#define SWZ(row, kbyte) ((kbyte) ^ ((((row) >> 1) & 3) << 4))
#define TILE_B (128 * 64)       // one 128-row x 64-byte tile = 8KB

// ---------------- split converts ----------------
__global__ __launch_bounds__(256)
void conv_split_x(const float* __restrict__ src,
                  __nv_bfloat16* __restrict__ hi, __nv_bfloat16* __restrict__ lo)
{
    size_t i = ((size_t)blockIdx.x * 256 + threadIdx.x) * 4;
    float4 v = *(const float4*)(src + i);
    float f[4] = {v.x, v.y, v.z, v.w};
    __nv_bfloat16 h[4], l[4];
#pragma unroll
    for (int c = 0; c < 4; c++) {
        h[c] = __float2bfloat16(f[c]);
        l[c] = __float2bfloat16(f[c] - __bfloat162float(h[c]));
    }
    *(__nv_bfloat162*)(hi + i)     = *(__nv_bfloat162*)&h[0];
    *(__nv_bfloat162*)(hi + i + 2) = *(__nv_bfloat162*)&h[2];
    *(__nv_bfloat162*)(lo + i)     = *(__nv_bfloat162*)&l[0];
    *(__nv_bfloat162*)(lo + i + 2) = *(__nv_bfloat162*)&l[2];
}

// W[k][n] -> transposed split Whi/Wlo[n][k]
__global__ __launch_bounds__(256)
void conv_split_wT(const float* __restrict__ W,
                   __nv_bfloat16* __restrict__ hi, __nv_bfloat16* __restrict__ lo)
{
    __shared__ float t[32][33];
    const int tx = threadIdx.x & 31, ty = threadIdx.x >> 5;
    const int bk = blockIdx.y * 32, bn = blockIdx.x * 32;
#pragma unroll
    for (int i = 0; i < 4; i++)
        t[ty + 8 * i][tx] = W[(size_t)(bk + ty + 8 * i) * EMBED + bn + tx];
    __syncthreads();
#pragma unroll
    for (int i = 0; i < 4; i++) {
        const int n = bn + ty + 8 * i, k = bk + tx;
        float v = t[tx][ty + 8 * i];
        __nv_bfloat16 h = __float2bfloat16(v);
        __nv_bfloat16 l = __float2bfloat16(v - __bfloat162float(h));
        hi[(size_t)n * EMBED + k] = h;
        lo[(size_t)n * EMBED + k] = l;
    }
}

__global__ void init_rowmax(unsigned* rm) { rm[blockIdx.x * 256 + threadIdx.x] = 0u; }

// ---------------- bf16x3 GEMM: C = X @ W (fp32-quality), + fp8 copy ----------------
#define XW_STAGE (4 * TILE_B)    // Ahi|Alo|Bhi|Blo = 32KB
__global__ __launch_bounds__(256, 2)
void xw_bf16x3(const __nv_bfloat16* __restrict__ Ahi, const __nv_bfloat16* __restrict__ Alo,
               const __nv_bfloat16* __restrict__ Bhi, const __nv_bfloat16* __restrict__ Blo,
               float* __restrict__ C, uint8_t* __restrict__ C8)
{
    extern __shared__ __align__(128) char smem[];
    const uint32_t sb = smem_u32(smem);

    const int tid  = threadIdx.x;
    const int lane = tid & 31;
    const int wid  = tid >> 5;
    const int wm   = wid >> 1;
    const int wn   = wid & 1;
    const int bm   = blockIdx.y * 128;
    const int bn   = blockIdx.x * 128;

    const int a_mrow = (lane & 7) + ((lane >> 3) & 1) * 8;
    const int a_kch  = (lane >> 4) & 1;
    const int b_row8 = ((lane >> 4) & 1) * 8 + (lane & 7);
    const int b_kch  = (lane >> 3) & 1;

    const int ld_row = tid >> 2, ld_ck = tid & 3;
    const uint32_t ld_off = ld_row * 64 + SWZ(ld_row, ld_ck * 16);
    const int ld_row2 = (tid + 256) >> 2, ld_ck2 = (tid + 256) & 3;
    const uint32_t ld_off2 = ld_row2 * 64 + SWZ(ld_row2, ld_ck2 * 16);

    float acc[2][8][4];
#pragma unroll
    for (int i = 0; i < 2; i++)
#pragma unroll
        for (int j = 0; j < 8; j++)
#pragma unroll
            for (int c = 0; c < 4; c++) acc[i][j][c] = 0.f;

    const int NCH = EMBED / 32;

#define XW_LOAD(st, kb_)                                                                  \
    do {                                                                                  \
        const uint32_t base = sb + (st) * XW_STAGE;                                       \
        const int ko = (kb_) * 32;                                                        \
        cp_async16(base + ld_off,              Ahi + (size_t)(bm + ld_row)  * EMBED + ko + ld_ck  * 8); \
        cp_async16(base + 8192  + ld_off,      Alo + (size_t)(bm + ld_row)  * EMBED + ko + ld_ck  * 8); \
        cp_async16(base + 16384 + ld_off,      Bhi + (size_t)(bn + ld_row)  * EMBED + ko + ld_ck  * 8); \
        cp_async16(base + 24576 + ld_off,      Blo + (size_t)(bn + ld_row)  * EMBED + ko + ld_ck  * 8); \
        cp_async16(base + ld_off2,             Ahi + (size_t)(bm + ld_row2) * EMBED + ko + ld_ck2 * 8); \
        cp_async16(base + 8192  + ld_off2,     Alo + (size_t)(bm + ld_row2) * EMBED + ko + ld_ck2 * 8); \
        cp_async16(base + 16384 + ld_off2,     Bhi + (size_t)(bn + ld_row2) * EMBED + ko + ld_ck2 * 8); \
        cp_async16(base + 24576 + ld_off2,     Blo + (size_t)(bn + ld_row2) * EMBED + ko + ld_ck2 * 8); \
    } while (0)

    XW_LOAD(0, 0); cp_commit();
    XW_LOAD(1, 1); cp_commit();

    for (int kb = 0; kb < NCH; ++kb) {
        if (kb < NCH - 2) cp_wait<1>(); else cp_wait<0>();
        __syncthreads();
        if (kb + 2 < NCH) { XW_LOAD((kb + 2) % 3, kb + 2); cp_commit(); }

        const uint32_t base = sb + (kb % 3) * XW_STAGE;
#pragma unroll
        for (int ks = 0; ks < 2; ks++) {
            uint32_t ahi[2][4], alo[2][4];
#pragma unroll
            for (int mt = 0; mt < 2; mt++) {
                int row = wm * 32 + mt * 16 + a_mrow;
                uint32_t o = row * 64 + SWZ(row, ks * 32 + a_kch * 16);
                ldsm_x4(ahi[mt][0], ahi[mt][1], ahi[mt][2], ahi[mt][3], base + o);
                ldsm_x4(alo[mt][0], alo[mt][1], alo[mt][2], alo[mt][3], base + 8192 + o);
            }
#pragma unroll
            for (int p = 0; p < 4; p++) {
                int row = wn * 64 + p * 16 + b_row8;
                uint32_t o = row * 64 + SWZ(row, ks * 32 + b_kch * 16);
                uint32_t h0, h1, h2, h3, l0, l1, l2, l3;
                ldsm_x4(h0, h1, h2, h3, base + 16384 + o);
                ldsm_x4(l0, l1, l2, l3, base + 24576 + o);
#pragma unroll
                for (int mt = 0; mt < 2; mt++) {
                    mma_bf16(acc[mt][2 * p],     ahi[mt], h0, h1);
                    mma_bf16(acc[mt][2 * p],     ahi[mt], l0, l1);
                    mma_bf16(acc[mt][2 * p],     alo[mt], h0, h1);
                    mma_bf16(acc[mt][2 * p + 1], ahi[mt], h2, h3);
                    mma_bf16(acc[mt][2 * p + 1], ahi[mt], l2, l3);
                    mma_bf16(acc[mt][2 * p + 1], alo[mt], h2, h3);
                }
            }
        }
        __syncthreads();
    }

    const int fr = lane >> 2, fc = (lane & 3) * 2;
#pragma unroll
    for (int mt = 0; mt < 2; mt++) {
        const int r0 = bm + wm * 32 + mt * 16 + fr;
#pragma unroll
        for (int nt = 0; nt < 8; nt++) {
            const int cc = bn + wn * 64 + nt * 8 + fc;
            *(float2*)(C + (size_t)r0 * EMBED + cc)       = make_float2(acc[mt][nt][0], acc[mt][nt][1]);
            *(float2*)(C + (size_t)(r0 + 8) * EMBED + cc) = make_float2(acc[mt][nt][2], acc[mt][nt][3]);
            *(uint16_t*)(C8 + (size_t)r0 * EMBED + cc) =
                pack_e4m3x2(acc[mt][nt][0] * FP8_SCALE, acc[mt][nt][1] * FP8_SCALE);
            *(uint16_t*)(C8 + (size_t)(r0 + 8) * EMBED + cc) =
                pack_e4m3x2(acc[mt][nt][2] * FP8_SCALE, acc[mt][nt][3] * FP8_SCALE);
        }
    }
}

// ---------------- fp8 QGMMA-ish: S = (Q K^T)/32 (bf16 store), 128x128, BK=64, 3 stages ----------------
#define QK_STAGE (2 * TILE_B)    // Q|K = 16KB (each 128 rows x 64 fp8 bytes)
__global__ __launch_bounds__(256, 2)
void qk_fp8(const uint8_t* __restrict__ Qb, const uint8_t* __restrict__ Kb,
            __nv_bfloat16* __restrict__ S, unsigned* __restrict__ rowmax)
{
    __shared__ __align__(128) char smem[3 * QK_STAGE];
    const uint32_t sb = smem_u32(smem);

    const int tid  = threadIdx.x;
    const int lane = tid & 31;
    const int wid  = tid >> 5;
    const int wm   = wid >> 1;
    const int wn   = wid & 1;
    const int bm   = blockIdx.y * 128;
    const int bn   = blockIdx.x * 128;

    const int a_mrow = (lane & 7) + ((lane >> 3) & 1) * 8;
    const int a_kch  = (lane >> 4) & 1;
    const int b_row8 = ((lane >> 4) & 1) * 8 + (lane & 7);
    const int b_kch  = (lane >> 3) & 1;

    const int ld_row = tid >> 2, ld_ck = tid & 3;
    const uint32_t ld_off = ld_row * 64 + SWZ(ld_row, ld_ck * 16);
    const int ld_row2 = (tid + 256) >> 2, ld_ck2 = (tid + 256) & 3;
    const uint32_t ld_off2 = ld_row2 * 64 + SWZ(ld_row2, ld_ck2 * 16);

    float acc[2][8][4];
#pragma unroll
    for (int i = 0; i < 2; i++)
#pragma unroll
        for (int j = 0; j < 8; j++)
#pragma unroll
            for (int c = 0; c < 4; c++) acc[i][j][c] = 0.f;

    const int NCH = EMBED / 64;   // 16 k-blocks of 64 fp8

#define QK8_LOAD(st, kb_)                                                                  \
    do {                                                                                   \
        const uint32_t base = sb + (st) * QK_STAGE;                                        \
        const int ko = (kb_) * 64;                                                         \
        cp_async16(base + ld_off,          Qb + (size_t)(bm + ld_row)  * EMBED + ko + ld_ck  * 16); \
        cp_async16(base + 8192 + ld_off,   Kb + (size_t)(bn + ld_row)  * EMBED + ko + ld_ck  * 16); \
        cp_async16(base + ld_off2,         Qb + (size_t)(bm + ld_row2) * EMBED + ko + ld_ck2 * 16); \
        cp_async16(base + 8192 + ld_off2,  Kb + (size_t)(bn + ld_row2) * EMBED + ko + ld_ck2 * 16); \
    } while (0)

    QK8_LOAD(0, 0); cp_commit();
    QK8_LOAD(1, 1); cp_commit();

    for (int kb = 0; kb < NCH; ++kb) {
        if (kb < NCH - 2) cp_wait<1>(); else cp_wait<0>();
        __syncthreads();
        if (kb + 2 < NCH) { QK8_LOAD((kb + 2) % 3, kb + 2); cp_commit(); }

        const uint32_t base = sb + (kb % 3) * QK_STAGE;
#pragma unroll
        for (int ks = 0; ks < 2; ks++) {        // two k32 steps in BK=64
            uint32_t af[2][4];
#pragma unroll
            for (int mt = 0; mt < 2; mt++) {
                int row = wm * 32 + mt * 16 + a_mrow;
                ldsm_x4(af[mt][0], af[mt][1], af[mt][2], af[mt][3],
                        base + row * 64 + SWZ(row, ks * 32 + a_kch * 16));
            }
#pragma unroll
            for (int p = 0; p < 4; p++) {
                int row = wn * 64 + p * 16 + b_row8;
                uint32_t b0, b1, b2, b3;
                ldsm_x4(b0, b1, b2, b3, base + 8192 + row * 64 + SWZ(row, ks * 32 + b_kch * 16));
#pragma unroll
                for (int mt = 0; mt < 2; mt++) {
                    mma_e4m3(acc[mt][2 * p],     af[mt], b0, b1);
                    mma_e4m3(acc[mt][2 * p + 1], af[mt], b2, b3);
                }
            }
        }
        __syncthreads();
    }

    const int g = lane >> 2, t4 = lane & 3;
    float rmax[4] = {-3.4e38f, -3.4e38f, -3.4e38f, -3.4e38f};
#pragma unroll
    for (int mt = 0; mt < 2; mt++) {
        const int r0 = bm + wm * 32 + mt * 16 + g;
#pragma unroll
        for (int nt = 0; nt < 8; nt++) {
            const int cc = bn + wn * 64 + nt * 8 + t4 * 2;
            float v0 = acc[mt][nt][0] * LOGIT_SCALE;
            float v1 = acc[mt][nt][1] * LOGIT_SCALE;
            float v2 = acc[mt][nt][2] * LOGIT_SCALE;
            float v3 = acc[mt][nt][3] * LOGIT_SCALE;
            *(__nv_bfloat162*)(S + (size_t)r0 * NTOK + cc)       = __floats2bfloat162_rn(v0, v1);
            *(__nv_bfloat162*)(S + (size_t)(r0 + 8) * NTOK + cc) = __floats2bfloat162_rn(v2, v3);
            rmax[mt * 2 + 0] = fmaxf(rmax[mt * 2 + 0], fmaxf(v0, v1));
            rmax[mt * 2 + 1] = fmaxf(rmax[mt * 2 + 1], fmaxf(v2, v3));
        }
    }
#pragma unroll
    for (int s = 0; s < 4; s++) {
        rmax[s] = fmaxf(rmax[s], __shfl_xor_sync(0xffffffff, rmax[s], 1));
        rmax[s] = fmaxf(rmax[s], __shfl_xor_sync(0xffffffff, rmax[s], 2));
    }
    if (t4 == 0) {
#pragma unroll
        for (int mt = 0; mt < 2; mt++) {
            atomicMax(&rowmax[bm + wm * 32 + mt * 16 + g],     enc_ord(rmax[mt * 2 + 0]));
            atomicMax(&rowmax[bm + wm * 32 + mt * 16 + g + 8], enc_ord(rmax[mt * 2 + 1]));
        }
    }
}

// ---------------- select finalists + exact rescore + softmax + gather ----------------
__global__ __launch_bounds__(256)
void select_rescore_gather(const __nv_bfloat16* __restrict__ S, const unsigned* __restrict__ rowmax,
                           const float* __restrict__ Q, const float* __restrict__ K,
                           const float* __restrict__ X, float* __restrict__ O)
{
    __shared__ float red[256];
    __shared__ int   s_cnt;
    __shared__ int   s_idx[CAP];
    __shared__ float s_lg[CAP];
    __shared__ float ws[NTOK];   // fallback-only scratch

    const int row = blockIdx.x;
    const int tid = threadIdx.x;
    const int wid = tid >> 5, lane = tid & 31;
    const float thr = dec_ord(rowmax[row]) - WINDOW;
    const uint4* p = (const uint4*)(S + (size_t)row * NTOK);

    if (tid == 0) s_cnt = 0;
    __syncthreads();

#pragma unroll
    for (int i = 0; i < 4; i++) {
        uint4 u = p[tid + i * 256];
        float f[8];
        __nv_bfloat162 h;
        h = *(__nv_bfloat162*)&u.x; f[0] = __low2float(h); f[1] = __high2float(h);
        h = *(__nv_bfloat162*)&u.y; f[2] = __low2float(h); f[3] = __high2float(h);
        h = *(__nv_bfloat162*)&u.z; f[4] = __low2float(h); f[5] = __high2float(h);
        h = *(__nv_bfloat162*)&u.w; f[6] = __low2float(h); f[7] = __high2float(h);
#pragma unroll
        for (int c = 0; c < 8; c++) {
            if (f[c] > thr) {
                int k = atomicAdd(&s_cnt, 1);
                if (k < CAP) s_idx[k] = (tid + i * 256) * 8 + c;
            }
        }
    }
    __syncthreads();
    const int cnt = s_cnt;
    const int col = tid * 4;

    if (cnt <= CAP) {
        // warp-parallel exact rescore: one warp per candidate
        const float* qr = Q + (size_t)row * EMBED;
        for (int t = wid; t < cnt; t += 8) {
            const float* kr = K + (size_t)s_idx[t] * EMBED;
            float d = 0.f;
            for (int e = lane * 4; e < EMBED; e += 128) {
                float4 a = *(const float4*)(qr + e);
                float4 b = *(const float4*)(kr + e);
                d += a.x * b.x + a.y * b.y + a.z * b.z + a.w * b.w;
            }
#pragma unroll
            for (int o = 16; o > 0; o >>= 1) d += __shfl_xor_sync(0xffffffff, d, o);
            if (lane == 0) s_lg[t] = d * 0.03125f;
        }
        __syncthreads();

        float mx = -3.402823466e+38f;
        for (int t = 0; t < cnt; t++) mx = fmaxf(mx, s_lg[t]);
        float sum = 0.f;
        for (int t = 0; t < cnt; t++) sum += expf(s_lg[t] - mx);
        const float inv = 1.f / sum;

        float a0 = 0.f, a1 = 0.f, a2 = 0.f, a3 = 0.f;
        for (int t = 0; t < cnt; t++) {
            const float w = expf(s_lg[t] - mx) * inv;
            const float4 x = *(const float4*)(X + (size_t)s_idx[t] * EMBED + col);
            a0 = fmaf(w, x.x, a0); a1 = fmaf(w, x.y, a1);
            a2 = fmaf(w, x.z, a2); a3 = fmaf(w, x.w, a3);
        }
        *(float4*)(O + (size_t)row * EMBED + col) = make_float4(a0, a1, a2, a3);
    } else {
        // pathological fallback: exact dense logits + dense softmax-gather
        const float* qr = Q + (size_t)row * EMBED;
        for (int j = tid; j < NTOK; j += 256) {
            const float* kr = K + (size_t)j * EMBED;
            float d = 0.f;
            for (int e = 0; e < EMBED; e += 4) {
                float4 a = *(const float4*)(qr + e);
                float4 b = *(const float4*)(kr + e);
                d += a.x * b.x + a.y * b.y + a.z * b.z + a.w * b.w;
            }
            ws[j] = d * 0.03125f;
        }
        __syncthreads();
        float mx = -3.402823466e+38f;
        for (int j = tid; j < NTOK; j += 256) mx = fmaxf(mx, ws[j]);
        red[tid] = mx; __syncthreads();
        for (int s = 128; s > 0; s >>= 1) {
            if (tid < s) red[tid] = fmaxf(red[tid], red[tid + s]);
            __syncthreads();
        }
        mx = red[0]; __syncthreads();
        float sum = 0.f;
        for (int j = tid; j < NTOK; j += 256) sum += expf(ws[j] - mx);
        red[tid] = sum; __syncthreads();
        for (int s = 128; s > 0; s >>= 1) {
            if (tid < s) red[tid] += red[tid + s];
            __syncthreads();
        }
        const float inv = 1.f / red[0];
        float a0 = 0.f, a1 = 0.f, a2 = 0.f, a3 = 0.f;
        for (int j = 0; j < NTOK; j++) {
            const float w = expf(ws[j] - mx) * inv;
            const float4 x = *(const float4*)(X + (size_t)j * EMBED + col);
            a0 = fmaf(w, x.x, a0); a1 = fmaf(w, x.y, a1);
            a2 = fmaf(w, x.z, a2); a3 = fmaf(w, x.w, a3);
        }
        *(float4*)(O + (size_t)row * EMBED + col) = make_float4(a0, a1, a2, a3);
    }
}

// ---------------- launch ----------------
extern "C" void kernel_launch(void* const* d_in, const int* in_sizes, int n_in,
                              void* d_out, int out_size)
{
    const float* Wr = (const float*)d_in[0];
    const float* We = (const float*)d_in[1];
    const float* X  = (const float*)d_in[2];
    float* out = (float*)d_out;

    float *Qp, *Kp;
    __nv_bfloat16 *Xhi, *Xlo, *Wrhi, *Wrlo, *Wehi, *Welo, *Sp;
    uint8_t *Q8, *K8;
    unsigned* rmx;
    cudaGetSymbolAddress((void**)&Qp,   g_Q);
    cudaGetSymbolAddress((void**)&Kp,   g_K);
    cudaGetSymbolAddress((void**)&Xhi,  g_Xhi);
    cudaGetSymbolAddress((void**)&Xlo,  g_Xlo);
    cudaGetSymbolAddress((void**)&Wrhi, g_Wrhi);
    cudaGetSymbolAddress((void**)&Wrlo, g_Wrlo);
    cudaGetSymbolAddress((void**)&Wehi, g_Wehi);
    cudaGetSymbolAddress((void**)&Welo, g_Welo);
    cudaGetSymbolAddress((void**)&Q8,   g_Q8);
    cudaGetSymbolAddress((void**)&K8,   g_K8);
    cudaGetSymbolAddress((void**)&Sp,   g_S);
    cudaGetSymbolAddress((void**)&rmx,  g_rowmax);

    // unconditional (no static guards allowed); host-side, capture-time only
    cudaFuncSetAttribute(xw_bf16x3, cudaFuncAttributeMaxDynamicSharedMemorySize, 3 * XW_STAGE);

    dim3 blk(256);
    conv_split_x<<<(NTOK * EMBED) / (256 * 4), blk>>>(X, Xhi, Xlo);
    conv_split_wT<<<dim3(32, 32), blk>>>(Wr, Wrhi, Wrlo);
    conv_split_wT<<<dim3(32, 32), blk>>>(We, Wehi, Welo);
    init_rowmax<<<NTOK / 256, blk>>>(rmx);
    // Q = X@Wr, K = X@We (bf16x3, fp32-quality) + fused fp8 copies
    xw_bf16x3<<<dim3(EMBED / 128, NTOK / 128), blk, 3 * XW_STAGE>>>(Xhi, Xlo, Wrhi, Wrlo, Qp, Q8);
    xw_bf16x3<<<dim3(EMBED / 128, NTOK / 128), blk, 3 * XW_STAGE>>>(Xhi, Xlo, Wehi, Welo, Kp, K8);
    // approx logits via fp8 MMA + rowmax
    qk_fp8<<<dim3(NTOK / 128, NTOK / 128), blk>>>(Q8, K8, Sp, rmx);
    // finalists: exact rescore + softmax + gather
    select_rescore_gather<<<NTOK, blk>>>(Sp, rmx, Qp, Kp, X, out);
}

// round 14
// speedup vs baseline: 1.1025x; 1.1025x over previous
#include <cuda_runtime.h>
#include <cuda_bf16.h>
#include <math.h>
#include <stdint.h>

#define EMBED 1024
#define NTOK  8192
#define CAP   64
#define WINDOW 100.0f

// ---------------- scratch (device globals) ----------------
__device__ float          g_Q[(size_t)NTOK * EMBED];
__device__ float          g_K[(size_t)NTOK * EMBED];
__device__ __nv_bfloat16  g_Xhi[(size_t)NTOK * EMBED];
__device__ __nv_bfloat16  g_Xlo[(size_t)NTOK * EMBED];
__device__ __nv_bfloat16  g_Wrhi[(size_t)EMBED * EMBED];
__device__ __nv_bfloat16  g_Wrlo[(size_t)EMBED * EMBED];
__device__ __nv_bfloat16  g_Wehi[(size_t)EMBED * EMBED];
__device__ __nv_bfloat16  g_Welo[(size_t)EMBED * EMBED];
__device__ __nv_bfloat16  g_Qb[(size_t)NTOK * EMBED];
__device__ __nv_bfloat16  g_Kb[(size_t)NTOK * EMBED];
__device__ __nv_bfloat16  g_S[(size_t)NTOK * NTOK];
__device__ unsigned       g_rowmax[NTOK];

// ---------------- helpers ----------------
__device__ __forceinline__ uint32_t smem_u32(const void* p) {
    uint32_t a;
    asm("{ .reg .u64 t; cvta.to.shared.u64 t, %1; cvt.u32.u64 %0, t; }" : "=r"(a) : "l"(p));
    return a;
}
__device__ __forceinline__ void cp_async16(uint32_t s, const void* g) {
    asm volatile("cp.async.cg.shared.global [%0], [%1], 16;" :: "r"(s), "l"(g));
}
__device__ __forceinline__ void cp_commit() { asm volatile("cp.async.commit_group;" ::: "memory"); }
template<int N>
__device__ __forceinline__ void cp_wait() { asm volatile("cp.async.wait_group %0;" :: "n"(N) : "memory"); }

__device__ __forceinline__ void ldsm_x4(uint32_t& r0, uint32_t& r1, uint32_t& r2, uint32_t& r3, uint32_t a) {
    asm volatile("ldmatrix.sync.aligned.m8n8.x4.shared.b16 {%0,%1,%2,%3}, [%4];"
                 : "=r"(r0), "=r"(r1), "=r"(r2), "=r"(r3) : "r"(a));
}
__device__ __forceinline__ void mma_bf16(float* d, const uint32_t* a, uint32_t b0, uint32_t b1) {
    asm volatile(
        "mma.sync.aligned.m16n8k16.row.col.f32.bf16.bf16.f32 "
        "{%0,%1,%2,%3}, {%4,%5,%6,%7}, {%8,%9}, {%0,%1,%2,%3};"
        : "+f"(d[0]), "+f"(d[1]), "+f"(d[2]), "+f"(d[3])
        : "r"(a[0]), "r"(a[1]), "r"(a[2]), "r"(a[3]), "r"(b0), "r"(b1));
}

__device__ __forceinline__ unsigned enc_ord(float f) {
    unsigned u = __float_as_uint(f);
    return (u & 0x80000000u) ? ~u : (u | 0x80000000u);
}
__device__ __forceinline__ float dec_ord(unsigned k) {
    unsigned u = (k & 0x80000000u) ? (k ^ 0x80000000u) : ~k;
    return __uint_as_float(u);
}

#define SWZ(row, kbyte) ((kbyte) ^ ((((row) >> 1) & 3) << 4))
#define TILE_B (128 * 64)       // one 128-row x 32-bf16 tile = 8KB

// ---------------- split convert X (+ fused rowmax init) ----------------
__global__ __launch_bounds__(256)
void conv_split_x(const float* __restrict__ src,
                  __nv_bfloat16* __restrict__ hi, __nv_bfloat16* __restrict__ lo,
                  unsigned* __restrict__ rm)
{
    if (blockIdx.x < NTOK / 256) rm[blockIdx.x * 256 + threadIdx.x] = 0u;

    size_t i = ((size_t)blockIdx.x * 256 + threadIdx.x) * 4;
    float4 v = *(const float4*)(src + i);
    float f[4] = {v.x, v.y, v.z, v.w};
    __nv_bfloat16 h[4], l[4];
#pragma unroll
    for (int c = 0; c < 4; c++) {
        h[c] = __float2bfloat16(f[c]);
        l[c] = __float2bfloat16(f[c] - __bfloat162float(h[c]));
    }
    *(__nv_bfloat162*)(hi + i)     = *(__nv_bfloat162*)&h[0];
    *(__nv_bfloat162*)(hi + i + 2) = *(__nv_bfloat162*)&h[2];
    *(__nv_bfloat162*)(lo + i)     = *(__nv_bfloat162*)&l[0];
    *(__nv_bfloat162*)(lo + i + 2) = *(__nv_bfloat162*)&l[2];
}

// W[k][n] -> transposed split hi/lo[n][k]; gridDim.z picks (Wr, We)
__global__ __launch_bounds__(256)
void conv_split_wT(const float* __restrict__ W0, const float* __restrict__ W1,
                   __nv_bfloat16* __restrict__ hi0, __nv_bfloat16* __restrict__ lo0,
                   __nv_bfloat16* __restrict__ hi1, __nv_bfloat16* __restrict__ lo1)
{
    const float* W = blockIdx.z ? W1 : W0;
    __nv_bfloat16* hi = blockIdx.z ? hi1 : hi0;
    __nv_bfloat16* lo = blockIdx.z ? lo1 : lo0;

    __shared__ float t[32][33];
    const int tx = threadIdx.x & 31, ty = threadIdx.x >> 5;
    const int bk = blockIdx.y * 32, bn = blockIdx.x * 32;
#pragma unroll
    for (int i = 0; i < 4; i++)
        t[ty + 8 * i][tx] = W[(size_t)(bk + ty + 8 * i) * EMBED + bn + tx];
    __syncthreads();
#pragma unroll
    for (int i = 0; i < 4; i++) {
        const int n = bn + ty + 8 * i, k = bk + tx;
        float v = t[tx][ty + 8 * i];
        __nv_bfloat16 h = __float2bfloat16(v);
        __nv_bfloat16 l = __float2bfloat16(v - __bfloat162float(h));
        hi[(size_t)n * EMBED + k] = h;
        lo[(size_t)n * EMBED + k] = l;
    }
}

// ---------------- bf16x3 GEMM: C = X @ W (fp32-quality), + bf16 copy ----------------
#define XW_STAGE (4 * TILE_B)    // Ahi|Alo|Bhi|Blo = 32KB
__global__ __launch_bounds__(256, 2)
void xw_bf16x3(const __nv_bfloat16* __restrict__ Ahi, const __nv_bfloat16* __restrict__ Alo,
               const __nv_bfloat16* __restrict__ Bhi, const __nv_bfloat16* __restrict__ Blo,
               float* __restrict__ C, __nv_bfloat16* __restrict__ Cb)
{
    extern __shared__ __align__(128) char smem[];
    const uint32_t sb = smem_u32(smem);

    const int tid  = threadIdx.x;
    const int lane = tid & 31;
    const int wid  = tid >> 5;
    const int wm   = wid >> 1;
    const int wn   = wid & 1;
    const int bm   = blockIdx.y * 128;
    const int bn   = blockIdx.x * 128;

    const int a_mrow = (lane & 7) + ((lane >> 3) & 1) * 8;
    const int a_kch  = (lane >> 4) & 1;
    const int b_row8 = ((lane >> 4) & 1) * 8 + (lane & 7);
    const int b_kch  = (lane >> 3) & 1;

    const int ld_row = tid >> 2, ld_ck = tid & 3;
    const uint32_t ld_off = ld_row * 64 + SWZ(ld_row, ld_ck * 16);
    const int ld_row2 = (tid + 256) >> 2, ld_ck2 = (tid + 256) & 3;
    const uint32_t ld_off2 = ld_row2 * 64 + SWZ(ld_row2, ld_ck2 * 16);

    float acc[2][8][4];
#pragma unroll
    for (int i = 0; i < 2; i++)
#pragma unroll
        for (int j = 0; j < 8; j++)
#pragma unroll
            for (int c = 0; c < 4; c++) acc[i][j][c] = 0.f;

    const int NCH = EMBED / 32;

#define XW_LOAD(st, kb_)                                                                  \
    do {                                                                                  \
        const uint32_t base = sb + (st) * XW_STAGE;                                       \
        const int ko = (kb_) * 32;                                                        \
        cp_async16(base + ld_off,              Ahi + (size_t)(bm + ld_row)  * EMBED + ko + ld_ck  * 8); \
        cp_async16(base + 8192  + ld_off,      Alo + (size_t)(bm + ld_row)  * EMBED + ko + ld_ck  * 8); \
        cp_async16(base + 16384 + ld_off,      Bhi + (size_t)(bn + ld_row)  * EMBED + ko + ld_ck  * 8); \
        cp_async16(base + 24576 + ld_off,      Blo + (size_t)(bn + ld_row)  * EMBED + ko + ld_ck  * 8); \
        cp_async16(base + ld_off2,             Ahi + (size_t)(bm + ld_row2) * EMBED + ko + ld_ck2 * 8); \
        cp_async16(base + 8192  + ld_off2,     Alo + (size_t)(bm + ld_row2) * EMBED + ko + ld_ck2 * 8); \
        cp_async16(base + 16384 + ld_off2,     Bhi + (size_t)(bn + ld_row2) * EMBED + ko + ld_ck2 * 8); \
        cp_async16(base + 24576 + ld_off2,     Blo + (size_t)(bn + ld_row2) * EMBED + ko + ld_ck2 * 8); \
    } while (0)

    XW_LOAD(0, 0); cp_commit();
    XW_LOAD(1, 1); cp_commit();

    for (int kb = 0; kb < NCH; ++kb) {
        if (kb < NCH - 2) cp_wait<1>(); else cp_wait<0>();
        __syncthreads();
        if (kb + 2 < NCH) { XW_LOAD((kb + 2) % 3, kb + 2); cp_commit(); }

        const uint32_t base = sb + (kb % 3) * XW_STAGE;
#pragma unroll
        for (int ks = 0; ks < 2; ks++) {
            uint32_t ahi[2][4], alo[2][4];
#pragma unroll
            for (int mt = 0; mt < 2; mt++) {
                int row = wm * 32 + mt * 16 + a_mrow;
                uint32_t o = row * 64 + SWZ(row, ks * 32 + a_kch * 16);
                ldsm_x4(ahi[mt][0], ahi[mt][1], ahi[mt][2], ahi[mt][3], base + o);
                ldsm_x4(alo[mt][0], alo[mt][1], alo[mt][2], alo[mt][3], base + 8192 + o);
            }
#pragma unroll
            for (int p = 0; p < 4; p++) {
                int row = wn * 64 + p * 16 + b_row8;
                uint32_t o = row * 64 + SWZ(row, ks * 32 + b_kch * 16);
                uint32_t h0, h1, h2, h3, l0, l1, l2, l3;
                ldsm_x4(h0, h1, h2, h3, base + 16384 + o);
                ldsm_x4(l0, l1, l2, l3, base + 24576 + o);
#pragma unroll
                for (int mt = 0; mt < 2; mt++) {
                    mma_bf16(acc[mt][2 * p],     ahi[mt], h0, h1);
                    mma_bf16(acc[mt][2 * p],     ahi[mt], l0, l1);
                    mma_bf16(acc[mt][2 * p],     alo[mt], h0, h1);
                    mma_bf16(acc[mt][2 * p + 1], ahi[mt], h2, h3);
                    mma_bf16(acc[mt][2 * p + 1], ahi[mt], l2, l3);
                    mma_bf16(acc[mt][2 * p + 1], alo[mt], h2, h3);
                }
            }
        }
        __syncthreads();
    }

    const int fr = lane >> 2, fc = (lane & 3) * 2;
#pragma unroll
    for (int mt = 0; mt < 2; mt++) {
        const int r0 = bm + wm * 32 + mt * 16 + fr;
#pragma unroll
        for (int nt = 0; nt < 8; nt++) {
            const int cc = bn + wn * 64 + nt * 8 + fc;
            *(float2*)(C + (size_t)r0 * EMBED + cc)       = make_float2(acc[mt][nt][0], acc[mt][nt][1]);
            *(float2*)(C + (size_t)(r0 + 8) * EMBED + cc) = make_float2(acc[mt][nt][2], acc[mt][nt][3]);
            *(__nv_bfloat162*)(Cb + (size_t)r0 * EMBED + cc) =
                __floats2bfloat162_rn(acc[mt][nt][0], acc[mt][nt][1]);
            *(__nv_bfloat162*)(Cb + (size_t)(r0 + 8) * EMBED + cc) =
                __floats2bfloat162_rn(acc[mt][nt][2], acc[mt][nt][3]);
        }
    }
}

// ---------------- HMMA bf16: S = (Q K^T)/32 (bf16 store), 128x128, BK=32, 3 stages ----------------
#define QK_STAGE (2 * TILE_B)    // Q|K = 16KB
__global__ __launch_bounds__(256, 2)
void qk_hmma(const __nv_bfloat16* __restrict__ Qb, const __nv_bfloat16* __restrict__ Kb,
             __nv_bfloat16* __restrict__ S, unsigned* __restrict__ rowmax)
{
    __shared__ __align__(128) char smem[3 * QK_STAGE];
    const uint32_t sb = smem_u32(smem);

    const int tid  = threadIdx.x;
    const int lane = tid & 31;
    const int wid  = tid >> 5;
    const int wm   = wid >> 1;
    const int wn   = wid & 1;
    const int bm   = blockIdx.y * 128;
    const int bn   = blockIdx.x * 128;

    const int a_mrow = (lane & 7) + ((lane >> 3) & 1) * 8;
    const int a_kch  = (lane >> 4) & 1;
    const int b_row8 = ((lane >> 4) & 1) * 8 + (lane & 7);
    const int b_kch  = (lane >> 3) & 1;

    const int ld_row = tid >> 2, ld_ck = tid & 3;
    const uint32_t ld_off = ld_row * 64 + SWZ(ld_row, ld_ck * 16);
    const int ld_row2 = (tid + 256) >> 2, ld_ck2 = (tid + 256) & 3;
    const uint32_t ld_off2 = ld_row2 * 64 + SWZ(ld_row2, ld_ck2 * 16);

    float acc[2][8][4];
#pragma unroll
    for (int i = 0; i < 2; i++)
#pragma unroll
        for (int j = 0; j < 8; j++)
#pragma unroll
            for (int c = 0; c < 4; c++) acc[i][j][c] = 0.f;

    const int NCH = EMBED / 32;

#define QK_LOAD(st, kb_)                                                                   \
    do {                                                                                   \
        const uint32_t base = sb + (st) * QK_STAGE;                                        \
        const int ko = (kb_) * 32;                                                         \
        cp_async16(base + ld_off,          Qb + (size_t)(bm + ld_row)  * EMBED + ko + ld_ck  * 8); \
        cp_async16(base + 8192 + ld_off,   Kb + (size_t)(bn + ld_row)  * EMBED + ko + ld_ck  * 8); \
        cp_async16(base + ld_off2,         Qb + (size_t)(bm + ld_row2) * EMBED + ko + ld_ck2 * 8); \
        cp_async16(base + 8192 + ld_off2,  Kb + (size_t)(bn + ld_row2) * EMBED + ko + ld_ck2 * 8); \
    } while (0)

    QK_LOAD(0, 0); cp_commit();
    QK_LOAD(1, 1); cp_commit();

    for (int kb = 0; kb < NCH; ++kb) {
        if (kb < NCH - 2) cp_wait<1>(); else cp_wait<0>();
        __syncthreads();
        if (kb + 2 < NCH) { QK_LOAD((kb + 2) % 3, kb + 2); cp_commit(); }

        const uint32_t base = sb + (kb % 3) * QK_STAGE;
#pragma unroll
        for (int ks = 0; ks < 2; ks++) {
            uint32_t af[2][4];
#pragma unroll
            for (int mt = 0; mt < 2; mt++) {
                int row = wm * 32 + mt * 16 + a_mrow;
                ldsm_x4(af[mt][0], af[mt][1], af[mt][2], af[mt][3],
                        base + row * 64 + SWZ(row, ks * 32 + a_kch * 16));
            }
#pragma unroll
            for (int p = 0; p < 4; p++) {
                int row = wn * 64 + p * 16 + b_row8;
                uint32_t b0, b1, b2, b3;
                ldsm_x4(b0, b1, b2, b3, base + 8192 + row * 64 + SWZ(row, ks * 32 + b_kch * 16));
#pragma unroll
                for (int mt = 0; mt < 2; mt++) {
                    mma_bf16(acc[mt][2 * p],     af[mt], b0, b1);
                    mma_bf16(acc[mt][2 * p + 1], af[mt], b2, b3);
                }
            }
        }
        __syncthreads();
    }

    const int g = lane >> 2, t4 = lane & 3;
    float rmax[4] = {-3.4e38f, -3.4e38f, -3.4e38f, -3.4e38f};
#pragma unroll
    for (int mt = 0; mt < 2; mt++) {
        const int r0 = bm + wm * 32 + mt * 16 + g;
#pragma unroll
        for (int nt = 0; nt < 8; nt++) {
            const int cc = bn + wn * 64 + nt * 8 + t4 * 2;
            float v0 = acc[mt][nt][0] * 0.03125f;
            float v1 = acc[mt][nt][1] * 0.03125f;
            float v2 = acc[mt][nt][2] * 0.03125f;
            float v3 = acc[mt][nt][3] * 0.03125f;
            *(__nv_bfloat162*)(S + (size_t)r0 * NTOK + cc)       = __floats2bfloat162_rn(v0, v1);
            *(__nv_bfloat162*)(S + (size_t)(r0 + 8) * NTOK + cc) = __floats2bfloat162_rn(v2, v3);
            rmax[mt * 2 + 0] = fmaxf(rmax[mt * 2 + 0], fmaxf(v0, v1));
            rmax[mt * 2 + 1] = fmaxf(rmax[mt * 2 + 1], fmaxf(v2, v3));
        }
    }
#pragma unroll
    for (int s = 0; s < 4; s++) {
        rmax[s] = fmaxf(rmax[s], __shfl_xor_sync(0xffffffff, rmax[s], 1));
        rmax[s] = fmaxf(rmax[s], __shfl_xor_sync(0xffffffff, rmax[s], 2));
    }
    if (t4 == 0) {
#pragma unroll
        for (int mt = 0; mt < 2; mt++) {
            atomicMax(&rowmax[bm + wm * 32 + mt * 16 + g],     enc_ord(rmax[mt * 2 + 0]));
            atomicMax(&rowmax[bm + wm * 32 + mt * 16 + g + 8], enc_ord(rmax[mt * 2 + 1]));
        }
    }
}

// ---------------- select finalists + exact rescore + softmax + gather ----------------
__global__ __launch_bounds__(256)
void select_rescore_gather(const __nv_bfloat16* __restrict__ S, const unsigned* __restrict__ rowmax,
                           const float* __restrict__ Q, const float* __restrict__ K,
                           const float* __restrict__ X, float* __restrict__ O)
{
    __shared__ float red[256];
    __shared__ int   s_cnt;
    __shared__ int   s_idx[CAP];
    __shared__ float s_lg[CAP];
    __shared__ float ws[NTOK];   // fallback-only scratch

    const int row = blockIdx.x;
    const int tid = threadIdx.x;
    const int wid = tid >> 5, lane = tid & 31;
    const float thr = dec_ord(rowmax[row]) - WINDOW;
    const uint4* p = (const uint4*)(S + (size_t)row * NTOK);

    if (tid == 0) s_cnt = 0;
    __syncthreads();

#pragma unroll
    for (int i = 0; i < 4; i++) {
        uint4 u = p[tid + i * 256];
        float f[8];
        __nv_bfloat162 h;
        h = *(__nv_bfloat162*)&u.x; f[0] = __low2float(h); f[1] = __high2float(h);
        h = *(__nv_bfloat162*)&u.y; f[2] = __low2float(h); f[3] = __high2float(h);
        h = *(__nv_bfloat162*)&u.z; f[4] = __low2float(h); f[5] = __high2float(h);
        h = *(__nv_bfloat162*)&u.w; f[6] = __low2float(h); f[7] = __high2float(h);
#pragma unroll
        for (int c = 0; c < 8; c++) {
            if (f[c] > thr) {
                int k = atomicAdd(&s_cnt, 1);
                if (k < CAP) s_idx[k] = (tid + i * 256) * 8 + c;
            }
        }
    }
    __syncthreads();
    const int cnt = s_cnt;
    const int col = tid * 4;

    if (cnt <= CAP) {
        // warp-parallel exact rescore: one warp per candidate
        const float* qr = Q + (size_t)row * EMBED;
        for (int t = wid; t < cnt; t += 8) {
            const float* kr = K + (size_t)s_idx[t] * EMBED;
            float d = 0.f;
            for (int e = lane * 4; e < EMBED; e += 128) {
                float4 a = *(const float4*)(qr + e);
                float4 b = *(const float4*)(kr + e);
                d += a.x * b.x + a.y * b.y + a.z * b.z + a.w * b.w;
            }
#pragma unroll
            for (int o = 16; o > 0; o >>= 1) d += __shfl_xor_sync(0xffffffff, d, o);
            if (lane == 0) s_lg[t] = d * 0.03125f;
        }
        __syncthreads();

        float mx = -3.402823466e+38f;
        for (int t = 0; t < cnt; t++) mx = fmaxf(mx, s_lg[t]);
        float sum = 0.f;
        for (int t = 0; t < cnt; t++) sum += expf(s_lg[t] - mx);
        const float inv = 1.f / sum;

        float a0 = 0.f, a1 = 0.f, a2 = 0.f, a3 = 0.f;
        for (int t = 0; t < cnt; t++) {
            const float w = expf(s_lg[t] - mx) * inv;
            const float4 x = *(const float4*)(X + (size_t)s_idx[t] * EMBED + col);
            a0 = fmaf(w, x.x, a0); a1 = fmaf(w, x.y, a1);
            a2 = fmaf(w, x.z, a2); a3 = fmaf(w, x.w, a3);
        }
        *(float4*)(O + (size_t)row * EMBED + col) = make_float4(a0, a1, a2, a3);
    } else {
        // pathological fallback: exact dense logits + dense softmax-gather
        const float* qr = Q + (size_t)row * EMBED;
        for (int j = tid; j < NTOK; j += 256) {
            const float* kr = K + (size_t)j * EMBED;
            float d = 0.f;
            for (int e = 0; e < EMBED; e += 4) {
                float4 a = *(const float4*)(qr + e);
                float4 b = *(const float4*)(kr + e);
                d += a.x * b.x + a.y * b.y + a.z * b.z + a.w * b.w;
            }
            ws[j] = d * 0.03125f;
        }
        __syncthreads();
        float mx = -3.402823466e+38f;
        for (int j = tid; j < NTOK; j += 256) mx = fmaxf(mx, ws[j]);
        red[tid] = mx; __syncthreads();
        for (int s = 128; s > 0; s >>= 1) {
            if (tid < s) red[tid] = fmaxf(red[tid], red[tid + s]);
            __syncthreads();
        }
        mx = red[0]; __syncthreads();
        float sum = 0.f;
        for (int j = tid; j < NTOK; j += 256) sum += expf(ws[j] - mx);
        red[tid] = sum; __syncthreads();
        for (int s = 128; s > 0; s >>= 1) {
            if (tid < s) red[tid] += red[tid + s];
            __syncthreads();
        }
        const float inv = 1.f / red[0];
        float a0 = 0.f, a1 = 0.f, a2 = 0.f, a3 = 0.f;
        for (int j = 0; j < NTOK; j++) {
            const float w = expf(ws[j] - mx) * inv;
            const float4 x = *(const float4*)(X + (size_t)j * EMBED + col);
            a0 = fmaf(w, x.x, a0); a1 = fmaf(w, x.y, a1);
            a2 = fmaf(w, x.z, a2); a3 = fmaf(w, x.w, a3);
        }
        *(float4*)(O + (size_t)row * EMBED + col) = make_float4(a0, a1, a2, a3);
    }
}

// ---------------- launch ----------------
extern "C" void kernel_launch(void* const* d_in, const int* in_sizes, int n_in,
                              void* d_out, int out_size)
{
    const float* Wr = (const float*)d_in[0];
    const float* We = (const float*)d_in[1];
    const float* X  = (const float*)d_in[2];
    float* out = (float*)d_out;

    float *Qp, *Kp;
    __nv_bfloat16 *Xhi, *Xlo, *Wrhi, *Wrlo, *Wehi, *Welo, *Qbp, *Kbp, *Sp;
    unsigned* rmx;
    cudaGetSymbolAddress((void**)&Qp,   g_Q);
    cudaGetSymbolAddress((void**)&Kp,   g_K);
    cudaGetSymbolAddress((void**)&Xhi,  g_Xhi);
    cudaGetSymbolAddress((void**)&Xlo,  g_Xlo);
    cudaGetSymbolAddress((void**)&Wrhi, g_Wrhi);
    cudaGetSymbolAddress((void**)&Wrlo, g_Wrlo);
    cudaGetSymbolAddress((void**)&Wehi, g_Wehi);
    cudaGetSymbolAddress((void**)&Welo, g_Welo);
    cudaGetSymbolAddress((void**)&Qbp,  g_Qb);
    cudaGetSymbolAddress((void**)&Kbp,  g_Kb);
    cudaGetSymbolAddress((void**)&Sp,   g_S);
    cudaGetSymbolAddress((void**)&rmx,  g_rowmax);

    // unconditional (no static guards allowed); host-side, capture-time only
    cudaFuncSetAttribute(xw_bf16x3, cudaFuncAttributeMaxDynamicSharedMemorySize, 3 * XW_STAGE);

    dim3 blk(256);
    conv_split_x<<<(NTOK * EMBED) / (256 * 4), blk>>>(X, Xhi, Xlo, rmx);
    conv_split_wT<<<dim3(32, 32, 2), blk>>>(Wr, We, Wrhi, Wrlo, Wehi, Welo);
    // Q = X@Wr, K = X@We (bf16x3, fp32-quality) + bf16 copies
    xw_bf16x3<<<dim3(EMBED / 128, NTOK / 128), blk, 3 * XW_STAGE>>>(Xhi, Xlo, Wrhi, Wrlo, Qp, Qbp);
    xw_bf16x3<<<dim3(EMBED / 128, NTOK / 128), blk, 3 * XW_STAGE>>>(Xhi, Xlo, Wehi, Welo, Kp, Kbp);
    // approx logits + rowmax
    qk_hmma<<<dim3(NTOK / 128, NTOK / 128), blk>>>(Qbp, Kbp, Sp, rmx);
    // finalists: exact rescore + softmax + gather
    select_rescore_gather<<<NTOK, blk>>>(Sp, rmx, Qp, Kp, X, out);
}